// round 15
// baseline (speedup 1.0000x reference)
#include <cuda_runtime.h>
#include <cuda_fp16.h>

#define NUM_USERS 100000
#define NUM_ITEMS 50000
#define N_NODES   150000
#define EMB_DIM   64
#define N_EDGES   4800000

#define VAL_BITS  14
#define VAL_MASK  ((1u << VAL_BITS) - 1u)          // 16383
#define VAL_SCALE ((float)VAL_MASK)
#define VAL_INV   (1.0f / VAL_SCALE)

#define SLOT_BITS 7
#define SLOTS     (1 << SLOT_BITS)                 // 128 slots/row (λ=32; P(overflow)≈0)

// Scratch (__device__ globals: allowed).
// g_pack slots [cnt, SLOTS) per row are NEVER written: zero at module load,
// and scatter rewrites exactly slots [0, cnt) identically on every replay
// (init re-zeroes g_cursor first). SpMM reads count rounded up to 4.
__device__ __half   g_h0[N_NODES * EMB_DIM];       // 19.2 MB fp16 x0
__device__ __half   g_h1[N_NODES * EMB_DIM];       // 19.2 MB fp16 e1
__device__ __half   g_h2[N_NODES * EMB_DIM];       // 19.2 MB fp16 e2
__device__ int      g_cursor[N_NODES];             // per-row edge count
__device__ unsigned g_pack[N_NODES << SLOT_BITS];  // ELL: (col<<14)|val_q14, 76.8 MB

// ---- PDL primitives (sm_90+) ----------------------------------------------
__device__ __forceinline__ void pdl_signal() {
    asm volatile("griddepcontrol.launch_dependents;" ::: "memory");
}
__device__ __forceinline__ void pdl_wait() {
    asm volatile("griddepcontrol.wait;" ::: "memory");
}

// ---------------------------------------------------------------------------
// init: h0 = fp16(concat(user,item)); counts = 0
// Signals dependents immediately so scatter can overlap its input reads.
// ---------------------------------------------------------------------------
__global__ void lgcn_init(const float* __restrict__ user_emb,
                          const float* __restrict__ item_emb) {
    pdl_signal();
    int i = blockIdx.x * blockDim.x + threadIdx.x;   // float4 index
    const int total4 = N_NODES * EMB_DIM / 4;
    if (i < N_NODES) g_cursor[i] = 0;
    if (i >= total4) return;
    const int uend4 = NUM_USERS * EMB_DIM / 4;
    float4 v = (i < uend4) ? ((const float4*)user_emb)[i]
                           : ((const float4*)item_emb)[i - uend4];
    __half2 h01 = __floats2half2_rn(v.x, v.y);
    __half2 h23 = __floats2half2_rn(v.z, v.w);
    ((uint2*)g_h0)[i] = make_uint2(*(unsigned*)&h01, *(unsigned*)&h23);
}

// ---------------------------------------------------------------------------
// scatter (PDL dependent of init): 8 edges / thread for deeper MLP on the
// LDG -> ATOMG -> STG chains. Loads edge inputs FIRST (independent of init),
// then waits, then does atomics + stores.
// ---------------------------------------------------------------------------
__device__ __forceinline__ void scat4(const int4& r, const int4& c, const float4& v) {
    {
        unsigned w = ((unsigned)c.x << VAL_BITS) | (unsigned)__float2int_rn(v.x * VAL_SCALE);
        g_pack[((unsigned)r.x << SLOT_BITS) + atomicAdd(&g_cursor[r.x], 1)] = w;
    }
    {
        unsigned w = ((unsigned)c.y << VAL_BITS) | (unsigned)__float2int_rn(v.y * VAL_SCALE);
        g_pack[((unsigned)r.y << SLOT_BITS) + atomicAdd(&g_cursor[r.y], 1)] = w;
    }
    {
        unsigned w = ((unsigned)c.z << VAL_BITS) | (unsigned)__float2int_rn(v.z * VAL_SCALE);
        g_pack[((unsigned)r.z << SLOT_BITS) + atomicAdd(&g_cursor[r.z], 1)] = w;
    }
    {
        unsigned w = ((unsigned)c.w << VAL_BITS) | (unsigned)__float2int_rn(v.w * VAL_SCALE);
        g_pack[((unsigned)r.w << SLOT_BITS) + atomicAdd(&g_cursor[r.w], 1)] = w;
    }
}

__global__ void lgcn_scatter(const float* __restrict__ vals,
                             const int*   __restrict__ rows,
                             const int*   __restrict__ cols) {
    int i = blockIdx.x * blockDim.x + threadIdx.x;   // 8 edges -> 2 int4 slots
    int j0 = i * 2, j1 = i * 2 + 1;
    bool a0 = (j0 < N_EDGES / 4), a1 = (j1 < N_EDGES / 4);
    int4 r0, c0, r1, c1;
    float4 v0, v1;
    if (a0) {
        r0 = ((const int4*)rows)[j0];
        c0 = ((const int4*)cols)[j0];
        v0 = ((const float4*)vals)[j0];
    }
    if (a1) {
        r1 = ((const int4*)rows)[j1];
        c1 = ((const int4*)cols)[j1];
        v1 = ((const float4*)vals)[j1];
    }
    pdl_wait();                              // init done: cursor == 0
    if (a0) scat4(r0, c0, v0);
    if (a1) scat4(r1, c1, v1);
}

// ---------------------------------------------------------------------------
// fp16 ELL SpMM core: 8 threads/row, one uint4 gather per edge per lane,
// pack words loaded 4-at-a-time (uint4; count rounded up to 4 — pad words
// are guaranteed zero), fp32 accumulation.
// ---------------------------------------------------------------------------
__device__ __forceinline__ void fma8(float* s, const uint4& a, float v) {
    const __half2* ph = (const __half2*)&a;
    #pragma unroll
    for (int k = 0; k < 4; k++) {
        float2 f = __half22float2(ph[k]);
        s[2*k]   += v * f.x;
        s[2*k+1] += v * f.y;
    }
}

__device__ __forceinline__ void spmm_row(const uint4* __restrict__ x4,
                                         int row, int lane, int cnt, float* s) {
    int p   = row << SLOT_BITS;
    int end = p + ((cnt + 3) & ~3);          // round up; pad words are 0
    for (; p < end; p += 4) {
        uint4 ww = *(const uint4*)&g_pack[p];   // aligned: p % 4 == 0
        uint4 a0 = __ldg(&x4[(ww.x >> VAL_BITS) * 8 + lane]);
        uint4 a1 = __ldg(&x4[(ww.y >> VAL_BITS) * 8 + lane]);
        uint4 a2 = __ldg(&x4[(ww.z >> VAL_BITS) * 8 + lane]);
        uint4 a3 = __ldg(&x4[(ww.w >> VAL_BITS) * 8 + lane]);
        fma8(s, a0, (float)(ww.x & VAL_MASK) * VAL_INV);
        fma8(s, a1, (float)(ww.y & VAL_MASK) * VAL_INV);
        fma8(s, a2, (float)(ww.z & VAL_MASK) * VAL_INV);
        fma8(s, a3, (float)(ww.w & VAL_MASK) * VAL_INV);
    }
}

// layers 1-2: y(fp16) = A x, no acc traffic.
__global__ void lgcn_spmm_mid(const __half* __restrict__ x,
                              __half* __restrict__ y) {
    pdl_signal();
    int t = blockIdx.x * blockDim.x + threadIdx.x;
    int row  = t >> 3;
    int lane = t & 7;
    if (row >= N_NODES) return;

    float s[8] = {0.f, 0.f, 0.f, 0.f, 0.f, 0.f, 0.f, 0.f};
    spmm_row((const uint4*)x, row, lane, g_cursor[row], s);

    __half2 h0 = __floats2half2_rn(s[0], s[1]);
    __half2 h1 = __floats2half2_rn(s[2], s[3]);
    __half2 h2 = __floats2half2_rn(s[4], s[5]);
    __half2 h3 = __floats2half2_rn(s[6], s[7]);
    uint4 out;
    out.x = *(unsigned*)&h0; out.y = *(unsigned*)&h1;
    out.z = *(unsigned*)&h2; out.w = *(unsigned*)&h3;
    ((uint4*)y)[row * 8 + lane] = out;
}

// layer 3 (PDL dependent of layer 2): prefetches x0(fp16, g_h0) + e1(g_h1) +
// cursor (all written >=1 kernel before layer 2) before waiting, then gathers
// e2 from g_h2. acc write-only.
__global__ void lgcn_spmm_final(float* __restrict__ acc) {
    int t = blockIdx.x * blockDim.x + threadIdx.x;
    int row  = t >> 3;
    int lane = t & 7;
    bool active = (row < N_NODES);

    uint4 x0w, e1w;
    int cnt = 0;
    if (active) {
        x0w = ((const uint4*)g_h0)[row * 8 + lane];
        e1w = ((const uint4*)g_h1)[row * 8 + lane];
        cnt = g_cursor[row];
    }
    pdl_wait();                              // layer 2 done: e2 (g_h2) ready
    if (!active) return;

    float s[8] = {0.f, 0.f, 0.f, 0.f, 0.f, 0.f, 0.f, 0.f};
    spmm_row((const uint4*)g_h2, row, lane, cnt, s);

    // add own-row x0 + e1 + e2 (all fp16)
    uint4 e2w = ((const uint4*)g_h2)[row * 8 + lane];
    fma8(s, x0w, 1.0f);
    fma8(s, e1w, 1.0f);
    fma8(s, e2w, 1.0f);

    float4* acc4 = (float4*)acc;
    int o = row * 16 + lane * 2;
    acc4[o]     = make_float4(s[0] * 0.25f, s[1] * 0.25f, s[2] * 0.25f, s[3] * 0.25f);
    acc4[o + 1] = make_float4(s[4] * 0.25f, s[5] * 0.25f, s[6] * 0.25f, s[7] * 0.25f);
}

// ---------------------------------------------------------------------------
// host: launch with PDL edges on scatter and final
// ---------------------------------------------------------------------------
static void launch_pdl(void* fn, int grid, int block, void** args) {
    cudaLaunchConfig_t cfg = {};
    cfg.gridDim  = dim3(grid);
    cfg.blockDim = dim3(block);
    cfg.dynamicSmemBytes = 0;
    cfg.stream = 0;
    cudaLaunchAttribute attr[1];
    attr[0].id = cudaLaunchAttributeProgrammaticStreamSerialization;
    attr[0].val.programmaticStreamSerializationAllowed = 1;
    cfg.attrs = attr;
    cfg.numAttrs = 1;
    cudaLaunchKernelExC(&cfg, fn, args);
}

extern "C" void kernel_launch(void* const* d_in, const int* in_sizes, int n_in,
                              void* d_out, int out_size) {
    const float* user_emb = (const float*)d_in[0];
    const float* item_emb = (const float*)d_in[1];
    const float* adj_vals = (const float*)d_in[2];
    const int*   adj_rows = (const int*)  d_in[3];
    const int*   adj_cols = (const int*)  d_in[4];
    float*       acc      = (float*)d_out;

    __half *h0, *h1, *h2;
    cudaGetSymbolAddress((void**)&h0, g_h0);
    cudaGetSymbolAddress((void**)&h1, g_h1);
    cudaGetSymbolAddress((void**)&h2, g_h2);

    const int total4  = N_NODES * EMB_DIM / 4;                 // 2.4M
    const int ew_grid = (total4 + 255) / 256;
    const int sc_grid = (N_EDGES / 8 + 255) / 256;             // 8 edges/thread
    const int sp_grid = (N_NODES * 8 + 255) / 256;             // 8 thr/row

    // h0 = fp16(x0); counts = 0   (signals dependents early)
    lgcn_init<<<ew_grid, 256>>>(user_emb, item_emb);

    // ELL build — PDL over init: edge reads overlap init
    {
        void* args[] = {(void*)&adj_vals, (void*)&adj_rows, (void*)&adj_cols};
        launch_pdl((void*)lgcn_scatter, sc_grid, 256, args);
    }

    // layer 1: e1 = A x0        (h0 -> h1)   normal launch
    lgcn_spmm_mid<<<sp_grid, 256>>>(h0, h1);
    // layer 2: e2 = A e1        (h1 -> h2)   normal launch
    lgcn_spmm_mid<<<sp_grid, 256>>>(h1, h2);

    // layer 3 — PDL over layer 2: x0/e1/cursor prefetch overlaps layer 2
    {
        void* args[] = {(void*)&acc};
        launch_pdl((void*)lgcn_spmm_final, sp_grid, 256, args);
    }
}

// round 16
// speedup vs baseline: 1.0224x; 1.0224x over previous
#include <cuda_runtime.h>
#include <cuda_fp16.h>

#define NUM_USERS 100000
#define NUM_ITEMS 50000
#define N_NODES   150000
#define EMB_DIM   64
#define N_EDGES   4800000

#define VAL_BITS  14
#define VAL_MASK  ((1u << VAL_BITS) - 1u)          // 16383
#define VAL_SCALE ((float)VAL_MASK)
#define VAL_INV   (1.0f / VAL_SCALE)

#define SLOT_BITS 7
#define SLOTS     (1 << SLOT_BITS)                 // 128 slots/row (λ=32; P(overflow)≈0)

// Scratch (__device__ globals: allowed).
// g_pack slots [cnt, SLOTS) per row are NEVER written: zero at module load,
// and scatter rewrites exactly slots [0, cnt) identically on every replay
// (init re-zeroes g_cursor first). SpMM reads count rounded up to 4.
__device__ __half   g_h0[N_NODES * EMB_DIM];       // 19.2 MB fp16 x0
__device__ __half   g_h1[N_NODES * EMB_DIM];       // 19.2 MB fp16 e1
__device__ __half   g_h2[N_NODES * EMB_DIM];       // 19.2 MB fp16 e2
__device__ int      g_cursor[N_NODES];             // per-row edge count
__device__ unsigned g_pack[N_NODES << SLOT_BITS];  // ELL: (col<<14)|val_q14, 76.8 MB

// ---- PDL primitives (sm_90+) ----------------------------------------------
__device__ __forceinline__ void pdl_signal() {
    asm volatile("griddepcontrol.launch_dependents;" ::: "memory");
}
__device__ __forceinline__ void pdl_wait() {
    asm volatile("griddepcontrol.wait;" ::: "memory");
}

// ---------------------------------------------------------------------------
// init: h0 = fp16(concat(user,item)); counts = 0
// Signals dependents immediately so scatter can overlap its input reads.
// ---------------------------------------------------------------------------
__global__ void lgcn_init(const float* __restrict__ user_emb,
                          const float* __restrict__ item_emb) {
    pdl_signal();
    int i = blockIdx.x * blockDim.x + threadIdx.x;   // float4 index
    const int total4 = N_NODES * EMB_DIM / 4;
    if (i < N_NODES) g_cursor[i] = 0;
    if (i >= total4) return;
    const int uend4 = NUM_USERS * EMB_DIM / 4;
    float4 v = (i < uend4) ? ((const float4*)user_emb)[i]
                           : ((const float4*)item_emb)[i - uend4];
    __half2 h01 = __floats2half2_rn(v.x, v.y);
    __half2 h23 = __floats2half2_rn(v.z, v.w);
    ((uint2*)g_h0)[i] = make_uint2(*(unsigned*)&h01, *(unsigned*)&h23);
}

// ---------------------------------------------------------------------------
// scatter (PDL dependent of init): 4 edges / thread (proven R14 shape).
// Loads edge inputs FIRST (independent of init), then waits, then scatters.
// ---------------------------------------------------------------------------
__global__ void lgcn_scatter(const float* __restrict__ vals,
                             const int*   __restrict__ rows,
                             const int*   __restrict__ cols) {
    int i = blockIdx.x * blockDim.x + threadIdx.x;
    int4 r, c;
    float4 v;
    bool active = (i < N_EDGES / 4);
    if (active) {
        r = ((const int4*)rows)[i];
        c = ((const int4*)cols)[i];
        v = ((const float4*)vals)[i];
    }
    pdl_wait();                              // init done: cursor == 0
    if (!active) return;
    {
        unsigned w = ((unsigned)c.x << VAL_BITS) | (unsigned)__float2int_rn(v.x * VAL_SCALE);
        g_pack[((unsigned)r.x << SLOT_BITS) + atomicAdd(&g_cursor[r.x], 1)] = w;
    }
    {
        unsigned w = ((unsigned)c.y << VAL_BITS) | (unsigned)__float2int_rn(v.y * VAL_SCALE);
        g_pack[((unsigned)r.y << SLOT_BITS) + atomicAdd(&g_cursor[r.y], 1)] = w;
    }
    {
        unsigned w = ((unsigned)c.z << VAL_BITS) | (unsigned)__float2int_rn(v.z * VAL_SCALE);
        g_pack[((unsigned)r.z << SLOT_BITS) + atomicAdd(&g_cursor[r.z], 1)] = w;
    }
    {
        unsigned w = ((unsigned)c.w << VAL_BITS) | (unsigned)__float2int_rn(v.w * VAL_SCALE);
        g_pack[((unsigned)r.w << SLOT_BITS) + atomicAdd(&g_cursor[r.w], 1)] = w;
    }
}

// ---------------------------------------------------------------------------
// fp16 ELL SpMM core: 8 threads/row, one uint4 gather per edge per lane,
// pack words loaded 4-at-a-time (uint4; count rounded up to 4 — pad words
// are guaranteed zero), fp32 accumulation.
// ---------------------------------------------------------------------------
__device__ __forceinline__ void fma8(float* s, const uint4& a, float v) {
    const __half2* ph = (const __half2*)&a;
    #pragma unroll
    for (int k = 0; k < 4; k++) {
        float2 f = __half22float2(ph[k]);
        s[2*k]   += v * f.x;
        s[2*k+1] += v * f.y;
    }
}

__device__ __forceinline__ void spmm_row(const uint4* __restrict__ x4,
                                         int row, int lane, int cnt, float* s) {
    int p   = row << SLOT_BITS;
    int end = p + ((cnt + 3) & ~3);          // round up; pad words are 0
    for (; p < end; p += 4) {
        uint4 ww = *(const uint4*)&g_pack[p];   // aligned: p % 4 == 0
        uint4 a0 = __ldg(&x4[(ww.x >> VAL_BITS) * 8 + lane]);
        uint4 a1 = __ldg(&x4[(ww.y >> VAL_BITS) * 8 + lane]);
        uint4 a2 = __ldg(&x4[(ww.z >> VAL_BITS) * 8 + lane]);
        uint4 a3 = __ldg(&x4[(ww.w >> VAL_BITS) * 8 + lane]);
        fma8(s, a0, (float)(ww.x & VAL_MASK) * VAL_INV);
        fma8(s, a1, (float)(ww.y & VAL_MASK) * VAL_INV);
        fma8(s, a2, (float)(ww.z & VAL_MASK) * VAL_INV);
        fma8(s, a3, (float)(ww.w & VAL_MASK) * VAL_INV);
    }
}

// layers 1-2: y(fp16) = A x, no acc traffic.
__global__ void lgcn_spmm_mid(const __half* __restrict__ x,
                              __half* __restrict__ y) {
    pdl_signal();
    int t = blockIdx.x * blockDim.x + threadIdx.x;
    int row  = t >> 3;
    int lane = t & 7;
    if (row >= N_NODES) return;

    float s[8] = {0.f, 0.f, 0.f, 0.f, 0.f, 0.f, 0.f, 0.f};
    spmm_row((const uint4*)x, row, lane, g_cursor[row], s);

    __half2 h0 = __floats2half2_rn(s[0], s[1]);
    __half2 h1 = __floats2half2_rn(s[2], s[3]);
    __half2 h2 = __floats2half2_rn(s[4], s[5]);
    __half2 h3 = __floats2half2_rn(s[6], s[7]);
    uint4 out;
    out.x = *(unsigned*)&h0; out.y = *(unsigned*)&h1;
    out.z = *(unsigned*)&h2; out.w = *(unsigned*)&h3;
    ((uint4*)y)[row * 8 + lane] = out;
}

// layer 3 (PDL dependent of layer 2): prefetches x0(fp16, g_h0) + e1(g_h1) +
// cursor (all written >=2 kernels before layer 2) before waiting, then gathers
// e2 from g_h2. acc is write-only (no fp32 input reads at all).
__global__ void lgcn_spmm_final(float* __restrict__ acc) {
    int t = blockIdx.x * blockDim.x + threadIdx.x;
    int row  = t >> 3;
    int lane = t & 7;
    bool active = (row < N_NODES);

    uint4 x0w, e1w;
    int cnt = 0;
    if (active) {
        x0w = ((const uint4*)g_h0)[row * 8 + lane];
        e1w = ((const uint4*)g_h1)[row * 8 + lane];
        cnt = g_cursor[row];
    }
    pdl_wait();                              // layer 2 done: e2 (g_h2) ready
    if (!active) return;

    float s[8] = {0.f, 0.f, 0.f, 0.f, 0.f, 0.f, 0.f, 0.f};
    spmm_row((const uint4*)g_h2, row, lane, cnt, s);

    // add own-row x0 + e1 + e2 (all fp16)
    uint4 e2w = ((const uint4*)g_h2)[row * 8 + lane];
    fma8(s, x0w, 1.0f);
    fma8(s, e1w, 1.0f);
    fma8(s, e2w, 1.0f);

    float4* acc4 = (float4*)acc;
    int o = row * 16 + lane * 2;
    acc4[o]     = make_float4(s[0] * 0.25f, s[1] * 0.25f, s[2] * 0.25f, s[3] * 0.25f);
    acc4[o + 1] = make_float4(s[4] * 0.25f, s[5] * 0.25f, s[6] * 0.25f, s[7] * 0.25f);
}

// ---------------------------------------------------------------------------
// host: launch with PDL edges on scatter and final
// ---------------------------------------------------------------------------
static void launch_pdl(void* fn, int grid, int block, void** args) {
    cudaLaunchConfig_t cfg = {};
    cfg.gridDim  = dim3(grid);
    cfg.blockDim = dim3(block);
    cfg.dynamicSmemBytes = 0;
    cfg.stream = 0;
    cudaLaunchAttribute attr[1];
    attr[0].id = cudaLaunchAttributeProgrammaticStreamSerialization;
    attr[0].val.programmaticStreamSerializationAllowed = 1;
    cfg.attrs = attr;
    cfg.numAttrs = 1;
    cudaLaunchKernelExC(&cfg, fn, args);
}

extern "C" void kernel_launch(void* const* d_in, const int* in_sizes, int n_in,
                              void* d_out, int out_size) {
    const float* user_emb = (const float*)d_in[0];
    const float* item_emb = (const float*)d_in[1];
    const float* adj_vals = (const float*)d_in[2];
    const int*   adj_rows = (const int*)  d_in[3];
    const int*   adj_cols = (const int*)  d_in[4];
    float*       acc      = (float*)d_out;

    __half *h0, *h1, *h2;
    cudaGetSymbolAddress((void**)&h0, g_h0);
    cudaGetSymbolAddress((void**)&h1, g_h1);
    cudaGetSymbolAddress((void**)&h2, g_h2);

    const int total4  = N_NODES * EMB_DIM / 4;                 // 2.4M
    const int ew_grid = (total4 + 255) / 256;
    const int sc_grid = (N_EDGES / 4 + 255) / 256;             // 4 edges/thread
    const int sp_grid = (N_NODES * 8 + 255) / 256;             // 8 thr/row

    // h0 = fp16(x0); counts = 0   (signals dependents early)
    lgcn_init<<<ew_grid, 256>>>(user_emb, item_emb);

    // ELL build — PDL over init: edge reads overlap init
    {
        void* args[] = {(void*)&adj_vals, (void*)&adj_rows, (void*)&adj_cols};
        launch_pdl((void*)lgcn_scatter, sc_grid, 256, args);
    }

    // layer 1: e1 = A x0        (h0 -> h1)   normal launch
    lgcn_spmm_mid<<<sp_grid, 256>>>(h0, h1);
    // layer 2: e2 = A e1        (h1 -> h2)   normal launch
    lgcn_spmm_mid<<<sp_grid, 256>>>(h1, h2);

    // layer 3 — PDL over layer 2: x0/e1/cursor prefetch overlaps layer 2
    {
        void* args[] = {(void*)&acc};
        launch_pdl((void*)lgcn_spmm_final, sp_grid, 256, args);
    }
}

// round 17
// speedup vs baseline: 1.0338x; 1.0111x over previous
#include <cuda_runtime.h>
#include <cuda_fp16.h>

#define NUM_USERS 100000
#define NUM_ITEMS 50000
#define N_NODES   150000
#define EMB_DIM   64
#define N_EDGES   4800000

#define VAL_BITS  14
#define VAL_MASK  ((1u << VAL_BITS) - 1u)          // 16383
#define VAL_SCALE ((float)VAL_MASK)
#define VAL_INV   (1.0f / VAL_SCALE)

#define SLOT_BITS 7
#define SLOTS     (1 << SLOT_BITS)                 // 128 slots/row (λ=32; P(overflow)≈0)

// Scratch (__device__ globals: allowed).
// g_pack slots [cnt, SLOTS) per row are NEVER written: zero at module load,
// and scatter rewrites exactly slots [0, cnt) identically on every replay
// (init re-zeroes g_cursor first). SpMM reads count rounded up to 4.
__device__ __half   g_h0[N_NODES * EMB_DIM];       // 19.2 MB fp16 embeddings (ping)
__device__ __half   g_h1[N_NODES * EMB_DIM];       // 19.2 MB fp16 embeddings (pong)
__device__ int      g_cursor[N_NODES];             // per-row edge count
__device__ unsigned g_pack[N_NODES << SLOT_BITS];  // ELL: (col<<14)|val_q14, 76.8 MB

// ---- PDL primitives (sm_90+) ----------------------------------------------
__device__ __forceinline__ void pdl_signal() {
    asm volatile("griddepcontrol.launch_dependents;" ::: "memory");
}
__device__ __forceinline__ void pdl_wait() {
    asm volatile("griddepcontrol.wait;" ::: "memory");
}
__device__ __forceinline__ void l2_prefetch(const void* p) {
    asm volatile("prefetch.global.L2 [%0];" :: "l"(p));
}

// ---------------------------------------------------------------------------
// init: h0 = fp16(concat(user,item)); counts = 0
// Signals dependents immediately so scatter can overlap its input reads.
// ---------------------------------------------------------------------------
__global__ void lgcn_init(const float* __restrict__ user_emb,
                          const float* __restrict__ item_emb) {
    pdl_signal();
    int i = blockIdx.x * blockDim.x + threadIdx.x;   // float4 index
    const int total4 = N_NODES * EMB_DIM / 4;
    if (i < N_NODES) g_cursor[i] = 0;
    if (i >= total4) return;
    const int uend4 = NUM_USERS * EMB_DIM / 4;
    float4 v = (i < uend4) ? ((const float4*)user_emb)[i]
                           : ((const float4*)item_emb)[i - uend4];
    __half2 h01 = __floats2half2_rn(v.x, v.y);
    __half2 h23 = __floats2half2_rn(v.z, v.w);
    ((uint2*)g_h0)[i] = make_uint2(*(unsigned*)&h01, *(unsigned*)&h23);
}

// ---------------------------------------------------------------------------
// scatter (PDL dependent of init): loads edge inputs FIRST (independent of
// init), then waits for init (cursor zeroed), then does atomics + stores.
// ---------------------------------------------------------------------------
__global__ void lgcn_scatter(const float* __restrict__ vals,
                             const int*   __restrict__ rows,
                             const int*   __restrict__ cols) {
    int i = blockIdx.x * blockDim.x + threadIdx.x;
    int4 r, c;
    float4 v;
    bool active = (i < N_EDGES / 4);
    if (active) {
        r = ((const int4*)rows)[i];
        c = ((const int4*)cols)[i];
        v = ((const float4*)vals)[i];
    }
    pdl_wait();                              // init done: cursor == 0
    if (!active) return;
    {
        unsigned w = ((unsigned)c.x << VAL_BITS) | (unsigned)__float2int_rn(v.x * VAL_SCALE);
        g_pack[((unsigned)r.x << SLOT_BITS) + atomicAdd(&g_cursor[r.x], 1)] = w;
    }
    {
        unsigned w = ((unsigned)c.y << VAL_BITS) | (unsigned)__float2int_rn(v.y * VAL_SCALE);
        g_pack[((unsigned)r.y << SLOT_BITS) + atomicAdd(&g_cursor[r.y], 1)] = w;
    }
    {
        unsigned w = ((unsigned)c.z << VAL_BITS) | (unsigned)__float2int_rn(v.z * VAL_SCALE);
        g_pack[((unsigned)r.z << SLOT_BITS) + atomicAdd(&g_cursor[r.z], 1)] = w;
    }
    {
        unsigned w = ((unsigned)c.w << VAL_BITS) | (unsigned)__float2int_rn(v.w * VAL_SCALE);
        g_pack[((unsigned)r.w << SLOT_BITS) + atomicAdd(&g_cursor[r.w], 1)] = w;
    }
}

// ---------------------------------------------------------------------------
// fp16 ELL SpMM core: 8 threads/row, one uint4 gather per edge per lane,
// pack words loaded 4-at-a-time (uint4; count rounded up to 4 — pad words
// are guaranteed zero), fp32 accumulation.
// ---------------------------------------------------------------------------
__device__ __forceinline__ void fma8(float* s, const uint4& a, float v) {
    const __half2* ph = (const __half2*)&a;
    #pragma unroll
    for (int k = 0; k < 4; k++) {
        float2 f = __half22float2(ph[k]);
        s[2*k]   += v * f.x;
        s[2*k+1] += v * f.y;
    }
}

__device__ __forceinline__ void spmm_row_cnt(const uint4* __restrict__ x4,
                                             int row, int lane, int cnt, float* s) {
    int p   = row << SLOT_BITS;
    int end = p + ((cnt + 3) & ~3);          // round up; pad words are 0
    for (; p < end; p += 4) {
        uint4 ww = *(const uint4*)&g_pack[p];   // aligned: p % 4 == 0
        uint4 a0 = __ldg(&x4[(ww.x >> VAL_BITS) * 8 + lane]);
        uint4 a1 = __ldg(&x4[(ww.y >> VAL_BITS) * 8 + lane]);
        uint4 a2 = __ldg(&x4[(ww.z >> VAL_BITS) * 8 + lane]);
        uint4 a3 = __ldg(&x4[(ww.w >> VAL_BITS) * 8 + lane]);
        fma8(s, a0, (float)(ww.x & VAL_MASK) * VAL_INV);
        fma8(s, a1, (float)(ww.y & VAL_MASK) * VAL_INV);
        fma8(s, a2, (float)(ww.z & VAL_MASK) * VAL_INV);
        fma8(s, a3, (float)(ww.w & VAL_MASK) * VAL_INV);
    }
}

// layers 1-2: y(fp16) = A x, no acc traffic.
// SECOND=0 (layer 1): normal launch; signals at entry so layer 2 starts early.
// SECOND=1 (layer 2): PDL dependent of layer 1 — pre-wait loads cursor and
//   L2-prefetches its pack row (both scatter outputs, complete long before),
//   then waits for layer 1, THEN signals (so final's pre-wait reads of h1
//   cannot race layer 1's writes).
template <int SECOND>
__global__ void lgcn_spmm_mid(const __half* __restrict__ x,
                              __half* __restrict__ y) {
    int t = blockIdx.x * blockDim.x + threadIdx.x;
    int row  = t >> 3;
    int lane = t & 7;
    bool active = (row < N_NODES);

    int cnt = 0;
    if (SECOND) {
        if (active) {
            cnt = g_cursor[row];
            if (lane == 0) {
                l2_prefetch(&g_pack[row << SLOT_BITS]);
                l2_prefetch(&g_pack[(row << SLOT_BITS) + 32]);
            }
        }
        pdl_wait();                          // layer 1 done: x (h1) ready
        pdl_signal();                        // now safe for final to prefetch h1
    } else {
        pdl_signal();                        // lets layer 2 pre-wait run early
        if (active) cnt = g_cursor[row];
    }
    if (!active) return;

    float s[8] = {0.f, 0.f, 0.f, 0.f, 0.f, 0.f, 0.f, 0.f};
    spmm_row_cnt((const uint4*)x, row, lane, cnt, s);

    __half2 h0 = __floats2half2_rn(s[0], s[1]);
    __half2 h1 = __floats2half2_rn(s[2], s[3]);
    __half2 h2 = __floats2half2_rn(s[4], s[5]);
    __half2 h3 = __floats2half2_rn(s[6], s[7]);
    uint4 out;
    out.x = *(unsigned*)&h0; out.y = *(unsigned*)&h1;
    out.z = *(unsigned*)&h2; out.w = *(unsigned*)&h3;
    ((uint4*)y)[row * 8 + lane] = out;
}

// layer 3 (PDL dependent of layer 2): prefetches x0(fp32 inputs) + e1(h1) +
// cursor — all complete once layer 2 signals (post-wait) — then gathers e2
// from h0. acc write-only.
__global__ void lgcn_spmm_final(const __half* __restrict__ e2buf,
                                const __half* __restrict__ e1buf,
                                const float* __restrict__ user_emb,
                                const float* __restrict__ item_emb,
                                float* __restrict__ acc) {
    int t = blockIdx.x * blockDim.x + threadIdx.x;
    int row  = t >> 3;
    int lane = t & 7;
    bool active = (row < N_NODES);

    float4 a0, a1;
    uint4 e1w;
    int cnt = 0;
    if (active) {
        const float4* src4 = (row < NUM_USERS)
            ? (const float4*)user_emb + (size_t)row * 16
            : (const float4*)item_emb + (size_t)(row - NUM_USERS) * 16;
        a0  = src4[lane * 2];
        a1  = src4[lane * 2 + 1];
        e1w = ((const uint4*)e1buf)[row * 8 + lane];
        cnt = g_cursor[row];
    }
    pdl_wait();                              // layer 2 done: e2 (h0) ready
    if (!active) return;

    float s[8] = {0.f, 0.f, 0.f, 0.f, 0.f, 0.f, 0.f, 0.f};
    spmm_row_cnt((const uint4*)e2buf, row, lane, cnt, s);

    // add own-row e1 + e2 (fp16)
    uint4 e2w = ((const uint4*)e2buf)[row * 8 + lane];
    fma8(s, e1w, 1.0f);
    fma8(s, e2w, 1.0f);

    float4* acc4 = (float4*)acc;
    int o = row * 16 + lane * 2;
    acc4[o]     = make_float4((a0.x + s[0]) * 0.25f, (a0.y + s[1]) * 0.25f,
                              (a0.z + s[2]) * 0.25f, (a0.w + s[3]) * 0.25f);
    acc4[o + 1] = make_float4((a1.x + s[4]) * 0.25f, (a1.y + s[5]) * 0.25f,
                              (a1.z + s[6]) * 0.25f, (a1.w + s[7]) * 0.25f);
}

// ---------------------------------------------------------------------------
// host: launch with PDL edges on scatter, layer 2, and final
// ---------------------------------------------------------------------------
static void launch_pdl(void* fn, int grid, int block, void** args) {
    cudaLaunchConfig_t cfg = {};
    cfg.gridDim  = dim3(grid);
    cfg.blockDim = dim3(block);
    cfg.dynamicSmemBytes = 0;
    cfg.stream = 0;
    cudaLaunchAttribute attr[1];
    attr[0].id = cudaLaunchAttributeProgrammaticStreamSerialization;
    attr[0].val.programmaticStreamSerializationAllowed = 1;
    cfg.attrs = attr;
    cfg.numAttrs = 1;
    cudaLaunchKernelExC(&cfg, fn, args);
}

extern "C" void kernel_launch(void* const* d_in, const int* in_sizes, int n_in,
                              void* d_out, int out_size) {
    const float* user_emb = (const float*)d_in[0];
    const float* item_emb = (const float*)d_in[1];
    const float* adj_vals = (const float*)d_in[2];
    const int*   adj_rows = (const int*)  d_in[3];
    const int*   adj_cols = (const int*)  d_in[4];
    float*       acc      = (float*)d_out;

    __half *h0, *h1;
    cudaGetSymbolAddress((void**)&h0, g_h0);
    cudaGetSymbolAddress((void**)&h1, g_h1);

    const int total4  = N_NODES * EMB_DIM / 4;                 // 2.4M
    const int ew_grid = (total4 + 255) / 256;
    const int sc_grid = (N_EDGES / 4 + 255) / 256;             // 4 edges/thread
    const int sp_grid = (N_NODES * 8 + 255) / 256;             // 8 thr/row

    // h0 = fp16(x0); counts = 0   (signals dependents early)
    lgcn_init<<<ew_grid, 256>>>(user_emb, item_emb);

    // ELL build — PDL over init: edge reads overlap init
    {
        void* args[] = {(void*)&adj_vals, (void*)&adj_rows, (void*)&adj_cols};
        launch_pdl((void*)lgcn_scatter, sc_grid, 256, args);
    }

    // layer 1: e1 = A x0        (h0 -> h1)   normal launch, signals at entry
    {
        const __half* x = h0; __half* y = h1;
        lgcn_spmm_mid<0><<<sp_grid, 256>>>(x, y);
    }
    // layer 2: e2 = A e1        (h1 -> h0)   PDL over layer 1
    {
        const __half* x = h1; __half* y = h0;
        void* args[] = {(void*)&x, (void*)&y};
        launch_pdl((void*)lgcn_spmm_mid<1>, sp_grid, 256, args);
    }
    // layer 3 — PDL over layer 2: x0/e1/cursor prefetch overlaps layer 2
    {
        const __half* e2buf = h0;
        const __half* e1buf = h1;
        void* args[] = {(void*)&e2buf, (void*)&e1buf,
                        (void*)&user_emb, (void*)&item_emb, (void*)&acc};
        launch_pdl((void*)lgcn_spmm_final, sp_grid, 256, args);
    }
}